// round 2
// baseline (speedup 1.0000x reference)
#include <cuda_runtime.h>
#include <math.h>

// ---------------------------------------------------------------------------
// Problem: B=32,T=512,N=4,E=16, NI=16,EI=8, HN=HE=128, MH=256, C=8
// M_node=65536, M_edge=262144
// ---------------------------------------------------------------------------

typedef unsigned long long u64;

#define SPB 5
#define LSTM_SMEM_FLOATS (96*512 + SPB*256 + SPB*128 + SPB*512)
#define LSTM_SMEM_BYTES  (LSTM_SMEM_FLOATS * 4)

// Static scratch (allocation-free rule)
__device__ float g_nA[65536 * 128];
__device__ float g_nB[65536 * 128];
__device__ float g_eA[262144 * 128];
__device__ float g_eB[262144 * 128];
__device__ float g_xzn[65536 * 512];
__device__ float g_xze[134217728];   // 262144 * 512
__device__ float g_c1[67108864];     // 262144 * 256

// ---- packed fp32x2 helpers (sm_100+ PTX) ----
__device__ __forceinline__ u64 pk2(float lo, float hi) {
    u64 r; asm("mov.b64 %0, {%1,%2};" : "=l"(r) : "f"(lo), "f"(hi)); return r;
}
__device__ __forceinline__ void up2(float& lo, float& hi, u64 v) {
    asm("mov.b64 {%0,%1}, %2;" : "=f"(lo), "=f"(hi) : "l"(v));
}
__device__ __forceinline__ void fma2(u64& c, u64 a, u64 b) {
    asm("fma.rn.f32x2 %0, %1, %2, %0;" : "+l"(c) : "l"(a), "l"(b));
}
__device__ __forceinline__ u64 add2(u64 a, u64 b) {
    u64 r; asm("add.rn.f32x2 %0, %1, %2;" : "=l"(r) : "l"(a), "l"(b)); return r;
}

__device__ __forceinline__ float sigmf(float x) { return 1.0f / (1.0f + __expf(-x)); }
__device__ __forceinline__ float tanhfast(float x) { return 1.0f - 2.0f / (__expf(2.0f * x) + 1.0f); }

// ---------------------------------------------------------------------------
// f32x2 SGEMM: C = act(A[M,K] @ B[K,N] + bias).  M%128==0, N%128==0, K%16==0.
// BM=BN=128, BK=16, 256 threads, 8x8 microtile as 4 row-pairs x 8 cols.
// ADJMIX: fused graph-conv mix over 4-row groups + bias + relu (node path).
// ---------------------------------------------------------------------------
template <int RELU, int HASBIAS, int ADJMIX>
__global__ __launch_bounds__(256) void sgemm2(
    const float* __restrict__ A, const float* __restrict__ B,
    const float* __restrict__ bias, float* __restrict__ C,
    int M, int N, int K)
{
    __shared__ float As[16][128];
    __shared__ float Bs[16][128];
    const int tid  = threadIdx.x;
    const int bm   = blockIdx.y * 128;
    const int bn   = blockIdx.x * 128;
    const int arow = tid >> 1;
    const int acol = (tid & 1) * 8;
    const int brow = tid >> 4;
    const int bcol = (tid & 15) * 8;
    const int tx   = (tid & 15) * 8;
    const int ty   = (tid >> 4) * 8;

    const float* Ap = A + (size_t)(bm + arow) * K + acol;
    const float* Bp = B + (size_t)brow * N + bn + bcol;

    // stage first tile in regs
    float4 a0 = *(const float4*)(Ap);
    float4 a1 = *(const float4*)(Ap + 4);
    float4 b0 = *(const float4*)(Bp);
    float4 b1 = *(const float4*)(Bp + 4);

    u64 acc[4][8];
#pragma unroll
    for (int i = 0; i < 4; i++)
#pragma unroll
        for (int j = 0; j < 8; j++) acc[i][j] = 0ull;

    int k0 = 0;
    for (;;) {
        As[acol + 0][arow] = a0.x; As[acol + 1][arow] = a0.y;
        As[acol + 2][arow] = a0.z; As[acol + 3][arow] = a0.w;
        As[acol + 4][arow] = a1.x; As[acol + 5][arow] = a1.y;
        As[acol + 6][arow] = a1.z; As[acol + 7][arow] = a1.w;
        *(float4*)&Bs[brow][bcol]     = b0;
        *(float4*)&Bs[brow][bcol + 4] = b1;
        __syncthreads();

        k0 += 16;
        bool more = (k0 < K);
        if (more) {   // prefetch next tile while computing this one
            a0 = *(const float4*)(Ap + k0);
            a1 = *(const float4*)(Ap + k0 + 4);
            b0 = *(const float4*)(Bp + (size_t)k0 * N);
            b1 = *(const float4*)(Bp + (size_t)k0 * N + 4);
        }

#pragma unroll
        for (int kk = 0; kk < 16; kk++) {
            ulonglong2 apA = *(const ulonglong2*)&As[kk][ty];
            ulonglong2 apB = *(const ulonglong2*)&As[kk][ty + 4];
            float4 c0 = *(const float4*)&Bs[kk][tx];
            float4 c1 = *(const float4*)&Bs[kk][tx + 4];
            u64 bd[8];
            bd[0] = pk2(c0.x, c0.x); bd[1] = pk2(c0.y, c0.y);
            bd[2] = pk2(c0.z, c0.z); bd[3] = pk2(c0.w, c0.w);
            bd[4] = pk2(c1.x, c1.x); bd[5] = pk2(c1.y, c1.y);
            bd[6] = pk2(c1.z, c1.z); bd[7] = pk2(c1.w, c1.w);
            u64 ap[4] = { apA.x, apA.y, apB.x, apB.y };
#pragma unroll
            for (int i = 0; i < 4; i++)
#pragma unroll
                for (int j = 0; j < 8; j++)
                    fma2(acc[i][j], ap[i], bd[j]);
        }
        if (!more) break;
        __syncthreads();
    }

    // unpack accumulators: v[r][j], r = local row ty+r
    float v[8][8];
#pragma unroll
    for (int i = 0; i < 4; i++)
#pragma unroll
        for (int j = 0; j < 8; j++)
            up2(v[2 * i][j], v[2 * i + 1][j], acc[i][j]);

    float bv[8];
    if (HASBIAS || ADJMIX) {
        *(float4*)&bv[0] = *(const float4*)&bias[bn + tx];
        *(float4*)&bv[4] = *(const float4*)&bias[bn + tx + 4];
    }

    if (ADJMIX) {
        // rows ty..ty+3 and ty+4..ty+7 are complete (b,t) node groups
#pragma unroll
        for (int g = 0; g < 2; g++) {
            float s[8];
#pragma unroll
            for (int j = 0; j < 8; j++)
                s[j] = v[4*g][j] + v[4*g+1][j] + v[4*g+2][j] + v[4*g+3][j];
#pragma unroll
            for (int r = 0; r < 4; r++) {
                float* Crow = C + (size_t)(bm + ty + 4*g + r) * N + bn + tx;
                float o[8];
#pragma unroll
                for (int j = 0; j < 8; j++)
                    o[j] = fmaxf((s[j] + v[4*g+r][j]) * 0.2f + bv[j], 0.f);
                *(float4*)(Crow)     = make_float4(o[0], o[1], o[2], o[3]);
                *(float4*)(Crow + 4) = make_float4(o[4], o[5], o[6], o[7]);
            }
        }
    } else {
#pragma unroll
        for (int r = 0; r < 8; r++) {
            float* Crow = C + (size_t)(bm + ty + r) * N + bn + tx;
            float o[8];
#pragma unroll
            for (int j = 0; j < 8; j++) {
                o[j] = v[r][j];
                if (HASBIAS) o[j] += bv[j];
                if (RELU)    o[j] = fmaxf(o[j], 0.f);
            }
            *(float4*)(Crow)     = make_float4(o[0], o[1], o[2], o[3]);
            *(float4*)(Crow + 4) = make_float4(o[4], o[5], o[6], o[7]);
        }
    }
}

// ---------------------------------------------------------------------------
// Old BK=8 SGEMM (kept only for K=8 first edge layer)
// ---------------------------------------------------------------------------
__global__ __launch_bounds__(256) void sgemm_k8(
    const float* __restrict__ A, const float* __restrict__ B,
    const float* __restrict__ bias, float* __restrict__ C,
    int M, int N, int K)
{
    __shared__ float As[8][128];
    __shared__ float Bs[8][128];
    const int tid  = threadIdx.x;
    const int bm   = blockIdx.y * 128;
    const int bn   = blockIdx.x * 128;
    const int arow = tid >> 1;
    const int acol = (tid & 1) * 4;
    const int brow = tid >> 5;
    const int bcol = (tid & 31) * 4;
    const int tx   = (tid & 15) * 8;
    const int ty   = (tid >> 4) * 8;

    const float* Ab = A + (size_t)(bm + arow) * K + acol;
    const float* Bb = B + (size_t)brow * N + bn + bcol;

    float acc[8][8];
#pragma unroll
    for (int i = 0; i < 8; i++)
#pragma unroll
        for (int j = 0; j < 8; j++) acc[i][j] = 0.f;

    for (int k0 = 0; k0 < K; k0 += 8) {
        float4 av = *(const float4*)(Ab + k0);
        float4 bv = *(const float4*)(Bb + (size_t)k0 * N);
        As[acol + 0][arow] = av.x;
        As[acol + 1][arow] = av.y;
        As[acol + 2][arow] = av.z;
        As[acol + 3][arow] = av.w;
        *(float4*)&Bs[brow][bcol] = bv;
        __syncthreads();
#pragma unroll
        for (int kk = 0; kk < 8; kk++) {
            float ar[8], br[8];
            *(float4*)&ar[0] = *(const float4*)&As[kk][ty];
            *(float4*)&ar[4] = *(const float4*)&As[kk][ty + 4];
            *(float4*)&br[0] = *(const float4*)&Bs[kk][tx];
            *(float4*)&br[4] = *(const float4*)&Bs[kk][tx + 4];
#pragma unroll
            for (int i = 0; i < 8; i++)
#pragma unroll
                for (int j = 0; j < 8; j++)
                    acc[i][j] += ar[i] * br[j];
        }
        __syncthreads();
    }

    float bv_[8];
    *(float4*)&bv_[0] = *(const float4*)&bias[bn + tx];
    *(float4*)&bv_[4] = *(const float4*)&bias[bn + tx + 4];
#pragma unroll
    for (int i = 0; i < 8; i++) {
        float* Crow = C + (size_t)(bm + ty + i) * N + bn + tx;
        float v[8];
#pragma unroll
        for (int j = 0; j < 8; j++)
            v[j] = fmaxf(acc[i][j] + bv_[j], 0.f);
        *(float4*)(Crow)     = make_float4(v[0], v[1], v[2], v[3]);
        *(float4*)(Crow + 4) = make_float4(v[4], v[5], v[6], v[7]);
    }
}

// ---------------------------------------------------------------------------
// Classifier GEMM with fused gather (f32x2, BK=16): M=262144, K=384, N=256
// ---------------------------------------------------------------------------
__global__ __launch_bounds__(256) void sgemm_c1(
    const float* __restrict__ hn, const float* __restrict__ he,
    const float* __restrict__ Wc1, const float* __restrict__ bc1,
    float* __restrict__ C)
{
    const int N = 256, K = 384;
    __shared__ float As[16][128];
    __shared__ float Bs[16][128];
    const int tid  = threadIdx.x;
    const int bm   = blockIdx.y * 128;
    const int bn   = blockIdx.x * 128;
    const int arow = tid >> 1;
    const int acol = (tid & 1) * 8;
    const int brow = tid >> 4;
    const int bcol = (tid & 15) * 8;
    const int tx   = (tid & 15) * 8;
    const int ty   = (tid >> 4) * 8;

    const int row = bm + arow;
    const int bt  = row >> 4;
    const int e   = row & 15;
    const float* seg0 = hn + ((size_t)bt * 4 + (e >> 2)) * 128 + acol;
    const float* seg1 = hn + ((size_t)bt * 4 + (e & 3)) * 128 + acol;
    const float* seg2 = he + (size_t)row * 128 + acol;

    const float* Bp = Wc1 + (size_t)brow * N + bn + bcol;

    float4 a0 = *(const float4*)(seg0);
    float4 a1 = *(const float4*)(seg0 + 4);
    float4 b0 = *(const float4*)(Bp);
    float4 b1 = *(const float4*)(Bp + 4);

    u64 acc[4][8];
#pragma unroll
    for (int i = 0; i < 4; i++)
#pragma unroll
        for (int j = 0; j < 8; j++) acc[i][j] = 0ull;

    int k0 = 0;
    for (;;) {
        As[acol + 0][arow] = a0.x; As[acol + 1][arow] = a0.y;
        As[acol + 2][arow] = a0.z; As[acol + 3][arow] = a0.w;
        As[acol + 4][arow] = a1.x; As[acol + 5][arow] = a1.y;
        As[acol + 6][arow] = a1.z; As[acol + 7][arow] = a1.w;
        *(float4*)&Bs[brow][bcol]     = b0;
        *(float4*)&Bs[brow][bcol + 4] = b1;
        __syncthreads();

        k0 += 16;
        bool more = (k0 < K);
        if (more) {
            const float* sp = (k0 < 128) ? seg0 : ((k0 < 256) ? seg1 : seg2);
            a0 = *(const float4*)(sp + (k0 & 127));
            a1 = *(const float4*)(sp + (k0 & 127) + 4);
            b0 = *(const float4*)(Bp + (size_t)k0 * N);
            b1 = *(const float4*)(Bp + (size_t)k0 * N + 4);
        }

#pragma unroll
        for (int kk = 0; kk < 16; kk++) {
            ulonglong2 apA = *(const ulonglong2*)&As[kk][ty];
            ulonglong2 apB = *(const ulonglong2*)&As[kk][ty + 4];
            float4 c0 = *(const float4*)&Bs[kk][tx];
            float4 c1 = *(const float4*)&Bs[kk][tx + 4];
            u64 bd[8];
            bd[0] = pk2(c0.x, c0.x); bd[1] = pk2(c0.y, c0.y);
            bd[2] = pk2(c0.z, c0.z); bd[3] = pk2(c0.w, c0.w);
            bd[4] = pk2(c1.x, c1.x); bd[5] = pk2(c1.y, c1.y);
            bd[6] = pk2(c1.z, c1.z); bd[7] = pk2(c1.w, c1.w);
            u64 ap[4] = { apA.x, apA.y, apB.x, apB.y };
#pragma unroll
            for (int i = 0; i < 4; i++)
#pragma unroll
                for (int j = 0; j < 8; j++)
                    fma2(acc[i][j], ap[i], bd[j]);
        }
        if (!more) break;
        __syncthreads();
    }

    float v[8][8];
#pragma unroll
    for (int i = 0; i < 4; i++)
#pragma unroll
        for (int j = 0; j < 8; j++)
            up2(v[2 * i][j], v[2 * i + 1][j], acc[i][j]);

    float bv[8];
    *(float4*)&bv[0] = *(const float4*)&bc1[bn + tx];
    *(float4*)&bv[4] = *(const float4*)&bc1[bn + tx + 4];
#pragma unroll
    for (int r = 0; r < 8; r++) {
        float* Crow = C + (size_t)(bm + ty + r) * N + bn + tx;
        float o[8];
#pragma unroll
        for (int j = 0; j < 8; j++)
            o[j] = fmaxf(v[r][j] + bv[j], 0.f);
        *(float4*)(Crow)     = make_float4(o[0], o[1], o[2], o[3]);
        *(float4*)(Crow + 4) = make_float4(o[4], o[5], o[6], o[7]);
    }
}

// ---------------------------------------------------------------------------
// Fused node+edge LSTM, f32x2 mainloop.
// Thread owns column pair (2*tid, 2*tid+1). h stored pre-duplicated in SMEM.
// Blocks 0..25: node (128 seqs). Blocks 26..128: edge (512 seqs). SPB=5.
// ---------------------------------------------------------------------------
__global__ __launch_bounds__(256, 1) void lstm2(
    const float* __restrict__ xz_n, const float* __restrict__ Whh_n, float* __restrict__ hn,
    const float* __restrict__ xz_e, const float* __restrict__ Whh_e, float* __restrict__ he)
{
    extern __shared__ float sm[];
    float* ws   = sm;                    // 96*512
    float* hdup = ws + 96 * 512;         // SPB*256 (duplicated h)
    float* csm  = hdup + SPB * 256;      // SPB*128
    float* zsm  = csm + SPB * 128;       // SPB*512

    const int tid = threadIdx.x;
    const int c2  = 2 * tid;

    const float* Whh;
    const float* xz;
    float* out;
    int seq0, nseq;
    long xbase[SPB], obase[SPB];
    long xstep, ostep;

    if (blockIdx.x < 26) {
        Whh = Whh_n; xz = xz_n; out = hn;
        seq0 = blockIdx.x * SPB; nseq = 128;
        xstep = 4 * 512; ostep = 4 * 128;
#pragma unroll
        for (int i = 0; i < SPB; i++) {
            int s = seq0 + i;
            long row = (long)(s >> 2) * 2048 + (s & 3);
            xbase[i] = row * 512;
            obase[i] = row * 128;
        }
    } else {
        Whh = Whh_e; xz = xz_e; out = he;
        seq0 = (blockIdx.x - 26) * SPB; nseq = 512;
        xstep = 16 * 512; ostep = 16 * 128;
#pragma unroll
        for (int i = 0; i < SPB; i++) {
            int s = seq0 + i;
            long row = (long)(s >> 4) * 8192 + (s & 15);
            xbase[i] = row * 512;
            obase[i] = row * 128;
        }
    }

    // Whh rows 0..95 -> SMEM; rows 96..127 -> registers as column-pair u64
    for (int idx = tid; idx < (96 * 512) / 4; idx += 256)
        ((float4*)ws)[idx] = ((const float4*)Whh)[idx];
    u64 wr[32];
#pragma unroll
    for (int r = 0; r < 32; r++)
        wr[r] = *(const u64*)&Whh[(96 + r) * 512 + c2];

    for (int idx = tid; idx < SPB * 256; idx += 256) hdup[idx] = 0.f;
    for (int idx = tid; idx < SPB * 128; idx += 256) csm[idx] = 0.f;
    __syncthreads();

    for (int t = 0; t < 512; t++) {
        u64 xv[SPB];
#pragma unroll
        for (int i = 0; i < SPB; i++)
            xv[i] = (seq0 + i < nseq)
                  ? *(const u64*)(xz + xbase[i] + (long)t * xstep + c2)
                  : 0ull;

        u64 acc[SPB];
#pragma unroll
        for (int i = 0; i < SPB; i++) acc[i] = 0ull;

        // rows 0..95 from SMEM weights
#pragma unroll 4
        for (int k = 0; k < 96; k += 2) {
            u64 w0 = *(const u64*)&ws[(size_t)k * 512 + c2];
            u64 w1 = *(const u64*)&ws[(size_t)(k + 1) * 512 + c2];
#pragma unroll
            for (int i = 0; i < SPB; i++) {
                ulonglong2 hd = *(const ulonglong2*)&hdup[i * 256 + 2 * k];
                fma2(acc[i], hd.x, w0);
                fma2(acc[i], hd.y, w1);
            }
        }
        // rows 96..127 from register weights
#pragma unroll
        for (int r = 0; r < 32; r += 2) {
#pragma unroll
            for (int i = 0; i < SPB; i++) {
                ulonglong2 hd = *(const ulonglong2*)&hdup[i * 256 + 2 * (96 + r)];
                fma2(acc[i], hd.x, wr[r]);
                fma2(acc[i], hd.y, wr[r + 1]);
            }
        }
#pragma unroll
        for (int i = 0; i < SPB; i++)
            *(u64*)&zsm[i * 512 + c2] = add2(acc[i], xv[i]);
        __syncthreads();

        // gates + state update
        for (int q = tid; q < SPB * 128; q += 256) {
            int i = q >> 7, hh = q & 127;
            const float* zrow = zsm + i * 512;
            float zi = zrow[hh];
            float zf = zrow[128 + hh];
            float zg = zrow[256 + hh];
            float zo = zrow[384 + hh];
            float cn = sigmf(zf) * csm[q] + sigmf(zi) * tanhfast(zg);
            float hv = sigmf(zo) * tanhfast(cn);
            csm[q] = cn;
            float2 hp; hp.x = hv; hp.y = hv;
            *(float2*)&hdup[i * 256 + 2 * hh] = hp;
            if (seq0 + i < nseq)
                out[obase[i] + (long)t * ostep + hh] = hv;
        }
        __syncthreads();
    }
}

// ---------------------------------------------------------------------------
// Final projection: out = c1[row,:256] @ Wc2 + bc2, C=8
// ---------------------------------------------------------------------------
__global__ __launch_bounds__(256) void final_k(
    const float* __restrict__ A, const float* __restrict__ W,
    const float* __restrict__ bias, float* __restrict__ out)
{
    __shared__ float ws[2048];
    __shared__ float as[32 * 264];
    const int tid = threadIdx.x;
    for (int i = tid; i < 2048; i += 256) ws[i] = W[i];

    long row0 = (long)blockIdx.x * 32;
    const float4* Ap = (const float4*)(A + row0 * 256);
    for (int i = tid; i < 2048; i += 256) {
        int r  = i >> 6;
        int c4 = i & 63;
        *(float4*)(as + r * 264 + c4 * 4) = Ap[(long)r * 64 + c4];
    }
    __syncthreads();

    int r = tid >> 3, c = tid & 7;
    float acc = bias[c];
    const float* arp = as + r * 264;
#pragma unroll 8
    for (int k = 0; k < 256; k++)
        acc += arp[k] * ws[k * 8 + c];
    out[(row0 + r) * 8 + c] = acc;
}

// ---------------------------------------------------------------------------
// Launch. Order chosen so ncu's 6th launch (-s 5 -c 1) = big Wih_e GEMM.
// ---------------------------------------------------------------------------
extern "C" void kernel_launch(void* const* d_in, const int* in_sizes, int n_in,
                              void* d_out, int out_size)
{
    const float* x_seq = (const float*)d_in[0];
    const float* ea    = (const float*)d_in[1];
    const float* Wn1   = (const float*)d_in[2];
    const float* bn1   = (const float*)d_in[3];
    const float* Wn2   = (const float*)d_in[4];
    const float* bn2   = (const float*)d_in[5];
    const float* We1   = (const float*)d_in[6];
    const float* be1   = (const float*)d_in[7];
    const float* We2   = (const float*)d_in[8];
    const float* be2   = (const float*)d_in[9];
    const float* Wg1   = (const float*)d_in[10];
    const float* bg1   = (const float*)d_in[11];
    const float* Wg2   = (const float*)d_in[12];
    const float* bg2   = (const float*)d_in[13];
    const float* Wef1  = (const float*)d_in[14];
    const float* bef1  = (const float*)d_in[15];
    const float* Wef2  = (const float*)d_in[16];
    const float* bef2  = (const float*)d_in[17];
    const float* Wih_n = (const float*)d_in[18];
    const float* Whh_n = (const float*)d_in[19];
    const float* b_n   = (const float*)d_in[20];
    const float* Wih_e = (const float*)d_in[21];
    const float* Whh_e = (const float*)d_in[22];
    const float* b_e   = (const float*)d_in[23];
    const float* Wc1   = (const float*)d_in[24];
    const float* bc1   = (const float*)d_in[25];
    const float* Wc2   = (const float*)d_in[26];
    const float* bc2   = (const float*)d_in[27];
    float* out = (float*)d_out;

    (void)in_sizes; (void)n_in; (void)out_size;

    cudaFuncSetAttribute(lstm2,
                         cudaFuncAttributeMaxDynamicSharedMemorySize,
                         LSTM_SMEM_BYTES);

    float* nA = g_nA; float* nB = g_nB;
    float* eA = g_eA; float* eB = g_eB;

    dim3 gn1(1, 512);     // node, N=128
    dim3 gn4(4, 512);     // node, N=512
    dim3 ge1(1, 2048);    // edge, N=128
    dim3 ge4(4, 2048);    // edge, N=512

    // 1-4: edge MLP chain
    sgemm_k8          <<<ge1, 256>>>(ea, We1, be1, eA, 262144, 128, 8);
    sgemm2<1, 1, 0>   <<<ge1, 256>>>(eA, We2, be2, eB, 262144, 128, 128);
    sgemm2<1, 1, 0>   <<<ge1, 256>>>(eB, Wef1, bef1, eA, 262144, 128, 128);
    sgemm2<1, 1, 0>   <<<ge1, 256>>>(eA, Wef2, bef2, eB, 262144, 128, 128);  // e4 in eB
    // 5: node layer 1
    sgemm2<1, 1, 0>   <<<gn1, 256>>>(x_seq, Wn1, bn1, nA, 65536, 128, 16);
    // 6: big edge LSTM input projection  (<- ncu profiles this one)
    sgemm2<0, 1, 0>   <<<ge4, 256>>>(eB, Wih_e, b_e, g_xze, 262144, 512, 128);
    // 7-9: node layer 2 + fused graph-conv layers
    sgemm2<1, 1, 0>   <<<gn1, 256>>>(nA, Wn2, bn2, nB, 65536, 128, 128);
    sgemm2<0, 1, 1>   <<<gn1, 256>>>(nB, Wg1, bg1, nA, 65536, 128, 128);   // mix fused
    sgemm2<0, 1, 1>   <<<gn1, 256>>>(nA, Wg2, bg2, nB, 65536, 128, 128);   // mix fused
    // 10: node LSTM input projection
    sgemm2<0, 1, 0>   <<<gn4, 256>>>(nB, Wih_n, b_n, g_xzn, 65536, 512, 128);
    // 11: fused node+edge LSTM -> hn in nA, he in eA
    lstm2<<<129, 256, LSTM_SMEM_BYTES>>>(g_xzn, Whh_n, nA, g_xze, Whh_e, eA);
    // 12-13: classifier
    sgemm_c1<<<dim3(2, 2048), 256>>>(nA, eA, Wc1, bc1, g_c1);
    final_k<<<8192, 256>>>(g_c1, Wc2, bc2, out);
}